// round 8
// baseline (speedup 1.0000x reference)
#include <cuda_runtime.h>
#include <math.h>

#define NBATCH 64
#define NSTEP  128
#define MEMD   128
#define NSLOT  20
#define OUTC   160
#define NGRP   14       // CTA groups per slot -> 280 CTAs, 2 per SM

__device__ float g_S [NBATCH * NSTEP * MEMD];
__device__ float g_O [NBATCH * NSTEP * OUTC];
__device__ float g_WK[OUTC * MEMD];
__device__ float g_BK[OUTC];
__device__ float g_VK[NSLOT * MEMD];
__device__ uint2 g_part[NSTEP][NSLOT][16];   // {sumsq bits, tag=t+1}; 14 used
__device__ float g_H [NBATCH * NSLOT * MEMD];

// ---------- helpers ----------
__device__ __forceinline__ void ffma2(unsigned long long &acc, unsigned long long a,
                                      unsigned long long b) {
    asm("fma.rn.f32x2 %0, %1, %2, %0;" : "+l"(acc) : "l"(a), "l"(b));
}
__device__ __forceinline__ unsigned long long pack2(float x) {
    unsigned long long r; asm("mov.b64 %0, {%1, %1};" : "=l"(r) : "f"(x)); return r;
}
__device__ __forceinline__ float2 up2(unsigned long long v) {
    float2 r; asm("mov.b64 {%0, %1}, %2;" : "=f"(r.x), "=f"(r.y) : "l"(v)); return r;
}
__device__ __forceinline__ unsigned smem_u32(const void* p) {
    return (unsigned)__cvta_generic_to_shared(p);
}
__device__ __forceinline__ void ldsA(unsigned addr, unsigned long long &m0,
                                     unsigned long long &m1) {
    asm("{\n\t"
        ".reg .b32 t0,t1,t2,t3;\n\t"
        "ld.shared.v4.b32 {t0,t1,t2,t3}, [%2];\n\t"
        "mov.b64 %0, {t0,t1};\n\t"
        "mov.b64 %1, {t2,t3};\n\t"
        "}" : "=l"(m0), "=l"(m1) : "r"(addr));
}
__device__ __forceinline__ unsigned long long ldsB(unsigned addr) {
    unsigned long long r;
    asm("{\n\t"
        ".reg .b32 t0,t1;\n\t"
        "ld.shared.v2.b32 {t0,t1}, [%1];\n\t"
        "mov.b64 %0, {t0,t1};\n\t"
        "}" : "=l"(r) : "r"(addr));
    return r;
}
__device__ __forceinline__ uint2 ldv2(const uint2* p) {
    uint2 v;
    asm volatile("ld.volatile.global.v2.u32 {%0,%1}, [%2];"
                 : "=r"(v.x), "=r"(v.y) : "l"(p) : "memory");
    return v;
}
__device__ __forceinline__ void stv2(uint2* p, uint2 v) {
    asm volatile("st.volatile.global.v2.u32 [%0], {%1,%2};"
                 :: "l"(p), "r"(v.x), "r"(v.y) : "memory");
}
__device__ __forceinline__ float sig(float x) { return 1.f / (1.f + __expf(-x)); }

// ---------- prologue ----------
__global__ void k_setup(const float* __restrict__ Ww, const float* __restrict__ Wb,
                        const float* __restrict__ sk, const float* __restrict__ Vw,
                        const float* __restrict__ Vb) {
    int bid = blockIdx.x, tid = threadIdx.x;
    if (bid < NSLOT) {
        float acc = Vb[tid];
        const float* skr = sk + bid * MEMD;
        const float* vwr = Vw + tid * MEMD;
        #pragma unroll 8
        for (int m = 0; m < MEMD; m++) acc += skr[m] * vwr[m];
        g_VK[bid * MEMD + tid] = acc;
    } else if (bid == NSLOT) {
        for (int idx = tid; idx < OUTC * MEMD; idx += 128) {
            int c = idx >> 7, m = idx & 127;
            float v = 0.f;
            if (c < 128)      v = Ww[c * MEMD + m];
            else if (c < 148) v = sk[(c - 128) * MEMD + m];
            g_WK[idx] = v;
        }
        for (int idx = tid; idx < OUTC; idx += 128)
            g_BK[idx] = (idx < 128) ? Wb[idx] : 0.f;
    } else {
        // zero tag buffer: 20480 uint4, 80 blocks x 128 thr x 2
        int base = (bid - 21) * 128 + tid;
        ((uint4*)g_part)[base]         = make_uint4(0u, 0u, 0u, 0u);
        ((uint4*)g_part)[base + 10240] = make_uint4(0u, 0u, 0u, 0u);
    }
}

__global__ void k_gather(const int* __restrict__ ids, const float* __restrict__ E) {
    int idx = blockIdx.x * 256 + threadIdx.x;
    int row = idx >> 5, q = idx & 31;
    int b = row >> 7, t = row & 127;
    int tok = __ldg(&ids[b * 4096 + t]);
    ((float4*)g_S)[row * 32 + q] = ((const float4*)E)[tok * 32 + q];
}

__global__ void __launch_bounds__(256) k_gemm() {
    __shared__ float Ss[64][33];
    __shared__ float Ks[OUTC][33];
    int tid = threadIdx.x, row0 = blockIdx.x * 64;
    int tx = tid & 15, ty = tid >> 4;
    float acc[4][10];
    #pragma unroll
    for (int i = 0; i < 4; i++)
        #pragma unroll
        for (int j = 0; j < 10; j++) acc[i][j] = 0.f;
    for (int kk = 0; kk < 128; kk += 32) {
        #pragma unroll
        for (int i = 0; i < 8; i++) {
            int idx = tid + i * 256, r = idx >> 5, k = idx & 31;
            Ss[r][k] = g_S[(row0 + r) * 128 + kk + k];
        }
        #pragma unroll
        for (int i = 0; i < 20; i++) {
            int idx = tid + i * 256, c = idx >> 5, k = idx & 31;
            Ks[c][k] = g_WK[c * 128 + kk + k];
        }
        __syncthreads();
        #pragma unroll
        for (int k = 0; k < 32; k++) {
            float a[4], bv[10];
            #pragma unroll
            for (int i = 0; i < 4; i++)  a[i]  = Ss[ty * 4 + i][k];
            #pragma unroll
            for (int j = 0; j < 10; j++) bv[j] = Ks[tx * 10 + j][k];
            #pragma unroll
            for (int i = 0; i < 4; i++)
                #pragma unroll
                for (int j = 0; j < 10; j++) acc[i][j] = fmaf(a[i], bv[j], acc[i][j]);
        }
        __syncthreads();
    }
    #pragma unroll
    for (int i = 0; i < 4; i++)
        #pragma unroll
        for (int j = 0; j < 10; j++) {
            int r = row0 + ty * 4 + i, c = tx * 10 + j;
            g_O[r * OUTC + c] = acc[i][j] + g_BK[c];
        }
}

// ---------- persistent scan: slot-major, 14-CTA groups, 2 CTAs/SM, poll warp ----------
__global__ void __launch_bounds__(288, 2) k_main(const float* __restrict__ Uw,
                                                 const float* __restrict__ Ub) {
    __shared__ __align__(16) float mem_s[128 * 8];      // raw mem[m][b], b<5 used
    __shared__ __align__(16) float pbuf[2 * 6 * 128];   // [mh][b][n] matmul partials
    __shared__ float red2_s[5];
    __shared__ float inv_sm;

    const int tid = threadIdx.x;
    const int wid = tid >> 5, lane = tid & 31;
    const int cta = blockIdx.x;
    const int j   = cta / NGRP, g = cta % NGRP;
    const int b0  = (g < 8) ? 5 * g : 40 + 4 * (g - 8);
    const int nb  = (g < 8) ? 5 : 4;

    // matmul mapping (tid < 256): column n, m-half mh
    const int n  = tid & 127;
    const int mh = tid >> 7;           // 0 for warps 0-3, 1 for warps 4-7
    const bool mmw = (tid < 256);

    // epilogue mapping: warp w = batch slot, lane handles n_i = lane + 32*i
    const int w = wid;
    const bool ew = (w < 5);
    const bool valid = (w < nb);
    const int batch = b0 + (valid ? w : 0);

    float uw[64];
    if (mmw) {
        const float4* up = (const float4*)(Uw + n * 128 + mh * 64);
        #pragma unroll
        for (int i = 0; i < 16; i++) {
            float4 v = up[i];
            uw[4*i] = v.x; uw[4*i+1] = v.y; uw[4*i+2] = v.z; uw[4*i+3] = v.w;
        }
    }

    float uvk[4], memv[4] = {0.f, 0.f, 0.f, 0.f};
    float s_c[4], w_c[4], skc = 0.f;
    const float* Sb = g_S + batch * 128 * 128;
    const float* Ob = g_O + batch * 128 * OUTC;
    if (ew) {
        #pragma unroll
        for (int i = 0; i < 4; i++) {
            int ni = lane + 32 * i;
            uvk[i] = Ub[ni] + g_VK[j * MEMD + ni];
            s_c[i] = Sb[ni];
            w_c[i] = Ob[ni];
        }
        float t0 = (lane == 0) ? Ob[128 + j] : 0.f;
        skc = __shfl_sync(~0u, t0, 0);
    }
    for (int idx = tid; idx < 128 * 8; idx += 288) mem_s[idx] = 0.f;
    if (tid == 0) inv_sm = 1.f;        // t=0: mem is exactly zero
    __syncthreads();

    const unsigned mbase = smem_u32(mem_s) + mh * 64 * 32;

    for (int t = 0; t < NSTEP; t++) {
        // ---- A. staging prefetch + gate dot (batch warps) ----
        float s_n[4], w_n[4], skn = 0.f, rawdot = 0.f;
        if (ew) {
            int tn = (t + 1) & 127;
            #pragma unroll
            for (int i = 0; i < 4; i++) {
                int ni = lane + 32 * i;
                s_n[i] = Sb[tn * 128 + ni];
                w_n[i] = Ob[tn * OUTC + ni];
            }
            float t0 = (lane == 0) ? Ob[tn * OUTC + 128 + j] : 0.f;
            skn = __shfl_sync(~0u, t0, 0);
            rawdot = s_c[0]*memv[0] + s_c[1]*memv[1] + s_c[2]*memv[2] + s_c[3]*memv[3];
            #pragma unroll
            for (int s = 16; s; s >>= 1) rawdot += __shfl_xor_sync(~0u, rawdot, s);
        }

        // ---- B. matmul (warps 0-7): 64 m-rows x (2 LDS.128 + 3 FFMA2) ----
        if (mmw) {
            unsigned long long a0 = 0ull, a1 = 0ull, a2 = 0ull;
            #pragma unroll
            for (int k = 0; k < 64; k++) {
                unsigned long long m0, m1;
                unsigned a = mbase + k * 32;
                ldsA(a, m0, m1);
                unsigned long long m2 = ldsB(a + 16);
                unsigned long long u2 = pack2(uw[k]);
                ffma2(a0, u2, m0);
                ffma2(a1, u2, m1);
                ffma2(a2, u2, m2);
            }
            float2 f0 = up2(a0), f1 = up2(a1), f2 = up2(a2);
            float* pb = pbuf + mh * 6 * 128 + n;
            pb[0]       = f0.x;
            pb[128]     = f0.y;
            pb[256]     = f1.x;
            pb[384]     = f1.y;
            pb[512]     = f2.x;
        }

        // ---- C. poll warp (warp 8): overlaps matmul ----
        if (wid == 8 && t) {
            const unsigned want = (unsigned)t;
            float val = 0.f;
            if (lane < NGRP) {
                const uint2* pp = &g_part[t - 1][j][lane];
                uint2 v;
                do { v = ldv2(pp); } while (v.y != want);
                val = __uint_as_float(v.x);
            }
            #pragma unroll
            for (int s = 16; s; s >>= 1) val += __shfl_xor_sync(~0u, val, s);
            if (lane == 0) inv_sm = rsqrtf(val);
        }
        __syncthreads();   // SYNC1: pbuf + inv_sm visible

        // ---- D. epilogue (batch warps) ----
        if (ew) {
            const float inv = inv_sm;
            float gg = sig(fmaf(inv, rawdot, skc));
            float sq = 0.f;
            #pragma unroll
            for (int i = 0; i < 4; i++) {
                int ni = lane + 32 * i;
                float hraw = pbuf[w * 128 + ni] + pbuf[(6 + w) * 128 + ni];
                float h = fmaxf(fmaf(inv, hraw, uvk[i] + w_c[i]), 0.f);
                if (valid) memv[i] = fmaf(memv[i], inv, gg * h);
                sq = fmaf(memv[i], memv[i], sq);
                mem_s[ni * 8 + w] = memv[i];
            }
            #pragma unroll
            for (int s = 16; s; s >>= 1) sq += __shfl_xor_sync(~0u, sq, s);
            if (lane == 0) red2_s[w] = sq;
            #pragma unroll
            for (int i = 0; i < 4; i++) { s_c[i] = s_n[i]; w_c[i] = w_n[i]; }
            skc = skn;
        }
        __syncthreads();   // SYNC2: mem(t+1) + red2_s visible

        // ---- E. publish (warp 8) ----
        if (wid == 8 && lane == 0) {
            float v = red2_s[0] + red2_s[1] + red2_s[2] + red2_s[3] + red2_s[4];
            uint2 pkt; pkt.x = __float_as_uint(v); pkt.y = (unsigned)(t + 1);
            stv2(&g_part[t][j][g], pkt);
        }
    }

    // ---- final normalization + writeback ----
    if (wid == 8) {
        const unsigned want = (unsigned)NSTEP;
        float val = 0.f;
        if (lane < NGRP) {
            const uint2* pp = &g_part[NSTEP - 1][j][lane];
            uint2 v;
            do { v = ldv2(pp); } while (v.y != want);
            val = __uint_as_float(v.x);
        }
        #pragma unroll
        for (int s = 16; s; s >>= 1) val += __shfl_xor_sync(~0u, val, s);
        if (lane == 0) inv_sm = rsqrtf(val);
    }
    __syncthreads();
    if (ew && valid) {
        const float inv = inv_sm;
        float* gh = g_H + batch * (NSLOT * MEMD) + j * MEMD;
        #pragma unroll
        for (int i = 0; i < 4; i++) gh[lane + 32 * i] = memv[i] * inv;
    }
}

// ---------- epilogue ----------
__global__ void k_epi(const int* __restrict__ q, const int* __restrict__ ans,
                      const float* __restrict__ E, const float* __restrict__ Hw,
                      const float* __restrict__ Hb, float* __restrict__ out) {
    __shared__ float red[4][NSLOT];
    __shared__ float p_s[NSLOT];
    __shared__ float u_s[MEMD];
    __shared__ float yr[4][2];
    int b = blockIdx.x, n = threadIdx.x, w = n >> 5, l = n & 31;

    float qv = 0.f;
    #pragma unroll
    for (int i = 0; i < 16; i++) qv += E[q[b * 16 + i] * MEMD + n];
    qv *= (1.f / 16.f);
    float a1 = 0.f, a2 = 0.f;
    #pragma unroll
    for (int i = 0; i < 8; i++) {
        a1 += E[ans[(b * 8 + i) * 2 + 0] * MEMD + n];
        a2 += E[ans[(b * 8 + i) * 2 + 1] * MEMD + n];
    }
    a1 *= 0.125f; a2 *= 0.125f;

    float hv[NSLOT], p[NSLOT];
    #pragma unroll
    for (int jj = 0; jj < NSLOT; jj++) {
        hv[jj] = g_H[b * (NSLOT * MEMD) + jj * MEMD + n];
        p[jj] = hv[jj] * qv;
    }
    #pragma unroll
    for (int s = 16; s; s >>= 1)
        #pragma unroll
        for (int jj = 0; jj < NSLOT; jj++) p[jj] += __shfl_xor_sync(~0u, p[jj], s);
    if (l == 0) {
        #pragma unroll
        for (int jj = 0; jj < NSLOT; jj++) red[w][jj] = p[jj];
    }
    __syncthreads();
    if (n == 0) {
        float d[NSLOT], mx = -1e30f;
        #pragma unroll
        for (int jj = 0; jj < NSLOT; jj++) {
            d[jj] = red[0][jj] + red[1][jj] + red[2][jj] + red[3][jj];
            mx = fmaxf(mx, d[jj]);
        }
        float sm = 0.f;
        #pragma unroll
        for (int jj = 0; jj < NSLOT; jj++) { d[jj] = expf(d[jj] - mx); sm += d[jj]; }
        float inv = 1.f / sm;
        #pragma unroll
        for (int jj = 0; jj < NSLOT; jj++) p_s[jj] = d[jj] * inv;
    }
    __syncthreads();

    float u = 0.f;
    #pragma unroll
    for (int jj = 0; jj < NSLOT; jj++) u = fmaf(p_s[jj], hv[jj], u);
    u_s[n] = u;
    __syncthreads();

    float r = qv + Hb[n];
    const float* hwr = Hw + n * MEMD;
    #pragma unroll 8
    for (int m = 0; m < MEMD; m++) r = fmaf(u_s[m], hwr[m], r);
    r = fmaxf(r, 0.f);

    float y1 = r * a1, y2 = r * a2;
    #pragma unroll
    for (int s = 16; s; s >>= 1) {
        y1 += __shfl_xor_sync(~0u, y1, s);
        y2 += __shfl_xor_sync(~0u, y2, s);
    }
    if (l == 0) { yr[w][0] = y1; yr[w][1] = y2; }
    __syncthreads();
    if (n == 0) {
        float s1 = yr[0][0] + yr[1][0] + yr[2][0] + yr[3][0];
        float s2 = yr[0][1] + yr[1][1] + yr[2][1] + yr[3][1];
        float mx = fmaxf(s1, s2);
        float e1 = expf(s1 - mx), e2 = expf(s2 - mx);
        float inv = 1.f / (e1 + e2);
        out[b * 2 + 0] = e1 * inv;
        out[b * 2 + 1] = e2 * inv;
    }
}

extern "C" void kernel_launch(void* const* d_in, const int* in_sizes, int n_in,
                              void* d_out, int out_size) {
    const int*   input_ids = (const int*)  d_in[0];
    const int*   question  = (const int*)  d_in[1];
    const int*   ans       = (const int*)  d_in[2];
    const float* E         = (const float*)d_in[3];
    const float* Uw        = (const float*)d_in[4];
    const float* Ub        = (const float*)d_in[5];
    const float* Vw        = (const float*)d_in[6];
    const float* Vb        = (const float*)d_in[7];
    const float* Ww        = (const float*)d_in[8];
    const float* Wb        = (const float*)d_in[9];
    const float* sk        = (const float*)d_in[10];
    const float* Hw        = (const float*)d_in[11];
    const float* Hb        = (const float*)d_in[12];
    float* out = (float*)d_out;

    k_setup <<<101, 128>>>(Ww, Wb, sk, Vw, Vb);
    k_gather<<<1024, 256>>>(input_ids, E);
    k_gemm  <<<128, 256>>>();
    k_main  <<<NSLOT * NGRP, 288>>>(Uw, Ub);
    k_epi   <<<64, 128>>>(question, ans, E, Hw, Hb, out);
}